// round 2
// baseline (speedup 1.0000x reference)
#include <cuda_runtime.h>
#include <cstdint>

// Problem constants
#define BB 2
#define SS 2048
#define DD 1024
#define HH 16
#define HD 64
#define MTOT (BB*SS)          // 4096
#define A_ELEMS (MTOT*DD)     // 4,194,304
#define KV_ELEMS (BB*HH*SS*HD) // 4,194,304

// Scratch (device globals; no allocation allowed)
__device__ float g_q[KV_ELEMS];       // q in (B,H,S,hd)
__device__ float g_attn[A_ELEMS];     // attention out, merged (B,S,D)

// ---------------------------------------------------------------------------
// SGEMM: C(M,N) = A(M,K) @ W(K,N) + bias(N)
// MODE 0: plain store to C (row-major, ld=N)
// MODE 1: scatter qkv: col<1024 -> q scratch, <2048 -> present_k, else present_v
// Tile 128x128x8, 256 threads, 8x8 per thread.
// ---------------------------------------------------------------------------
template<int MODE>
__global__ __launch_bounds__(256) void sgemm_kernel(
    const float* __restrict__ A, const float* __restrict__ W,
    const float* __restrict__ bias, float* __restrict__ C,
    float* __restrict__ pk, float* __restrict__ pv, float* __restrict__ qo,
    int M, int N, int K)
{
    __shared__ float As[8][128];   // As[k][m]
    __shared__ float Bs[8][128];   // Bs[k][n]

    const int bm = blockIdx.y * 128;
    const int bn = blockIdx.x * 128;
    const int tid = threadIdx.x;
    const int tr = tid >> 4;       // 0..15
    const int tc = tid & 15;       // 0..15

    // load indices
    const int a_row = tid >> 1;            // 0..127
    const int a_c4  = (tid & 1) << 2;      // 0 or 4
    const int b_row = tid >> 5;            // 0..7
    const int b_c4  = (tid & 31) << 2;     // 0..124

    float acc[8][8];
    #pragma unroll
    for (int i = 0; i < 8; i++)
        #pragma unroll
        for (int j = 0; j < 8; j++) acc[i][j] = 0.f;

    const float* Aptr = A + (size_t)(bm + a_row) * K + a_c4;
    const float* Wptr = W + (size_t)b_row * N + bn + b_c4;

    for (int k0 = 0; k0 < K; k0 += 8) {
        float4 av = *(const float4*)(Aptr + k0);
        As[a_c4 + 0][a_row] = av.x;
        As[a_c4 + 1][a_row] = av.y;
        As[a_c4 + 2][a_row] = av.z;
        As[a_c4 + 3][a_row] = av.w;
        float4 bv = *(const float4*)(Wptr + (size_t)k0 * N);
        *(float4*)&Bs[b_row][b_c4] = bv;
        __syncthreads();

        #pragma unroll
        for (int k = 0; k < 8; k++) {
            float4 a0 = *(float4*)&As[k][tr * 8];
            float4 a1 = *(float4*)&As[k][tr * 8 + 4];
            float4 b0 = *(float4*)&Bs[k][tc * 8];
            float4 b1 = *(float4*)&Bs[k][tc * 8 + 4];
            float af[8] = {a0.x,a0.y,a0.z,a0.w,a1.x,a1.y,a1.z,a1.w};
            float bf[8] = {b0.x,b0.y,b0.z,b0.w,b1.x,b1.y,b1.z,b1.w};
            #pragma unroll
            for (int i = 0; i < 8; i++)
                #pragma unroll
                for (int j = 0; j < 8; j++)
                    acc[i][j] += af[i] * bf[j];
        }
        __syncthreads();
    }

    #pragma unroll
    for (int i = 0; i < 8; i++) {
        int gm = bm + tr * 8 + i;
        #pragma unroll
        for (int j = 0; j < 8; j++) {
            int gn = bn + tc * 8 + j;
            float val = acc[i][j] + bias[gn];
            if (MODE == 0) {
                C[(size_t)gm * N + gn] = val;
            } else {
                int part = gn >> 10;        // 0:q 1:k 2:v
                int col  = gn & 1023;
                int h = col >> 6, d = col & 63;
                int b = gm >> 11, s = gm & 2047;
                size_t idx = (((size_t)(b * HH + h)) * SS + s) * HD + d;
                float* dst = (part == 0) ? qo : (part == 1) ? pk : pv;
                dst[idx] = val;
            }
        }
    }
}

// ---------------------------------------------------------------------------
// Flash attention, fp32. BM=64 queries/block, BN=32 keys/tile, 256 threads.
// Each thread owns 1 query row (r=tid/4) and 16 output cols (cg=tid%4).
// Scores: thread computes 8 score cols (j0=cg*8).
// ---------------------------------------------------------------------------
__global__ __launch_bounds__(256) void attn_kernel(
    const float* __restrict__ Q, const float* __restrict__ Kg,
    const float* __restrict__ Vg, float* __restrict__ Og)
{
    const int qt = blockIdx.x;        // 0..31
    const int bh = blockIdx.y;        // 0..31  (b*16+h)
    const int q0 = qt * 64;

    const float* qb = Q  + ((size_t)bh * SS + q0) * HD;
    const float* kb = Kg + (size_t)bh * SS * HD;
    const float* vb = Vg + (size_t)bh * SS * HD;

    __shared__ float Qs[64][65];
    __shared__ float KVs[32][68];
    __shared__ float Ss[64][33];

    const int tid = threadIdx.x;

    // Load Q tile (64x64): 1024 float4s
    for (int e = tid; e < 1024; e += 256) {
        int r = e >> 4, c = (e & 15) << 2;
        float4 v = *(const float4*)(qb + r * 64 + c);
        Qs[r][c] = v.x; Qs[r][c+1] = v.y; Qs[r][c+2] = v.z; Qs[r][c+3] = v.w;
    }

    const int r  = tid >> 2;     // query row 0..63
    const int cg = tid & 3;
    const int j0 = cg * 8;
    const int c0 = cg * 16;
    const int qi = q0 + r;

    float m_i = -1e30f, l_i = 0.f;
    float o[16];
    #pragma unroll
    for (int c = 0; c < 16; c++) o[c] = 0.f;

    const int n_kt = 2 * qt + 2;
    __syncthreads();

    for (int kt = 0; kt < n_kt; kt++) {
        const int k0 = kt * 32;
        // load K tile (32x64): 512 float4s, rows 0..31
        for (int e = tid; e < 512; e += 256) {
            int rr = e >> 4, cc = (e & 15) << 2;
            float4 v = *(const float4*)(kb + (size_t)(k0 + rr) * 64 + cc);
            KVs[rr][cc] = v.x; KVs[rr][cc+1] = v.y; KVs[rr][cc+2] = v.z; KVs[rr][cc+3] = v.w;
        }
        __syncthreads();

        // scores: S[r][j0..j0+7]
        float acc[8];
        #pragma unroll
        for (int jj = 0; jj < 8; jj++) acc[jj] = 0.f;
        #pragma unroll 4
        for (int d = 0; d < 64; d++) {
            float qv = Qs[r][d];
            #pragma unroll
            for (int jj = 0; jj < 8; jj++)
                acc[jj] += qv * KVs[j0 + jj][d];
        }
        #pragma unroll
        for (int jj = 0; jj < 8; jj++) {
            int jg = k0 + j0 + jj;
            float s = (jg <= qi) ? acc[jj] * 0.125f : -1e10f;
            Ss[r][j0 + jj] = s;
        }
        __syncthreads();

        // softmax update (reads Ss row into regs) ...
        float p[32];
        float mt = -1e30f;
        #pragma unroll
        for (int j = 0; j < 32; j++) { p[j] = Ss[r][j]; mt = fmaxf(mt, p[j]); }
        float m_new = fmaxf(m_i, mt);
        float scale = __expf(m_i - m_new);
        float sum = 0.f;
        #pragma unroll
        for (int j = 0; j < 32; j++) { p[j] = __expf(p[j] - m_new); sum += p[j]; }
        l_i = l_i * scale + sum;
        m_i = m_new;
        #pragma unroll
        for (int c = 0; c < 16; c++) o[c] *= scale;

        // ... then load V tile into KVs (after all threads done with K)
        __syncthreads();
        for (int e = tid; e < 512; e += 256) {
            int rr = e >> 4, cc = (e & 15) << 2;
            float4 v = *(const float4*)(vb + (size_t)(k0 + rr) * 64 + cc);
            KVs[rr][cc] = v.x; KVs[rr][cc+1] = v.y; KVs[rr][cc+2] = v.z; KVs[rr][cc+3] = v.w;
        }
        __syncthreads();

        // O += P @ V
        #pragma unroll 8
        for (int j = 0; j < 32; j++) {
            float pv = p[j];
            #pragma unroll
            for (int c = 0; c < 16; c++)
                o[c] += pv * KVs[j][c0 + c];
        }
        __syncthreads();
    }

    // write merged (B,S,D): row = b*S + (q0+r), col = h*64 + c0 + c
    const int b = bh >> 4, h = bh & 15;
    const float inv = 1.f / l_i;
    float* ob = Og + ((size_t)(b * SS + q0 + r)) * DD + h * HD + c0;
    #pragma unroll
    for (int c = 0; c < 16; c++) ob[c] = o[c] * inv;
}

// ---------------------------------------------------------------------------
extern "C" void kernel_launch(void* const* d_in, const int* in_sizes, int n_in,
                              void* d_out, int out_size)
{
    const float* x        = (const float*)d_in[0];
    const float* c_attn_w = (const float*)d_in[1];
    const float* c_attn_b = (const float*)d_in[2];
    const float* c_proj_w = (const float*)d_in[3];
    const float* c_proj_b = (const float*)d_in[4];

    float* out   = (float*)d_out;
    float* a_out = out;                       // (B,S,D)
    float* pk    = out + A_ELEMS;             // present[0] = k (B,H,S,hd)
    float* pv    = pk + KV_ELEMS;             // present[1] = v

    float* qsym;
    cudaGetSymbolAddress((void**)&qsym, g_q);
    float* asym;
    cudaGetSymbolAddress((void**)&asym, g_attn);

    // 1) qkv = x @ c_attn_w + b  -> scatter q/k/v
    {
        dim3 grid(3 * DD / 128, MTOT / 128);   // (24, 32)
        sgemm_kernel<1><<<grid, 256>>>(x, c_attn_w, c_attn_b,
                                       nullptr, pk, pv, qsym,
                                       MTOT, 3 * DD, DD);
    }
    // 2) attention -> g_attn (merged B,S,D)
    {
        dim3 grid(SS / 64, BB * HH);           // (32, 32)
        attn_kernel<<<grid, 256>>>(qsym, pk, pv, asym);
    }
    // 3) a = attn @ c_proj_w + b -> d_out
    {
        dim3 grid(DD / 128, MTOT / 128);       // (8, 32)
        sgemm_kernel<0><<<grid, 256>>>(asym, c_proj_w, c_proj_b,
                                       a_out, nullptr, nullptr, nullptr,
                                       MTOT, DD, DD);
    }
}

// round 3
// speedup vs baseline: 3.4111x; 3.4111x over previous
#include <cuda_runtime.h>
#include <cstdint>

// Problem constants
#define BB 2
#define SS 2048
#define DD 1024
#define HH 16
#define HD 64
#define MTOT (BB*SS)           // 4096
#define A_ELEMS (MTOT*DD)      // 4,194,304
#define KV_ELEMS (BB*HH*SS*HD) // 4,194,304

// Scratch (device globals; no allocation allowed)
__device__ float g_q[KV_ELEMS];       // q in (B,H,S,hd)
__device__ float g_attn[A_ELEMS];     // attention out, merged (B,S,D)

// ---------------------------------------------------------------------------
// SGEMM: C(M,N) = A(M,K) @ W(K,N) + bias(N)
// MODE 0: plain store. MODE 1: scatter q->scratch, k/v->present.
// ---------------------------------------------------------------------------
template<int MODE>
__global__ __launch_bounds__(256) void sgemm_kernel(
    const float* __restrict__ A, const float* __restrict__ W,
    const float* __restrict__ bias, float* __restrict__ C,
    float* __restrict__ pk, float* __restrict__ pv, float* __restrict__ qo,
    int M, int N, int K)
{
    __shared__ float As[8][128];
    __shared__ float Bs[8][128];

    const int bm = blockIdx.y * 128;
    const int bn = blockIdx.x * 128;
    const int tid = threadIdx.x;
    const int tr = tid >> 4;
    const int tc = tid & 15;

    const int a_row = tid >> 1;
    const int a_c4  = (tid & 1) << 2;
    const int b_row = tid >> 5;
    const int b_c4  = (tid & 31) << 2;

    float acc[8][8];
    #pragma unroll
    for (int i = 0; i < 8; i++)
        #pragma unroll
        for (int j = 0; j < 8; j++) acc[i][j] = 0.f;

    const float* Aptr = A + (size_t)(bm + a_row) * K + a_c4;
    const float* Wptr = W + (size_t)b_row * N + bn + b_c4;

    for (int k0 = 0; k0 < K; k0 += 8) {
        float4 av = *(const float4*)(Aptr + k0);
        As[a_c4 + 0][a_row] = av.x;
        As[a_c4 + 1][a_row] = av.y;
        As[a_c4 + 2][a_row] = av.z;
        As[a_c4 + 3][a_row] = av.w;
        float4 bv = *(const float4*)(Wptr + (size_t)k0 * N);
        *(float4*)&Bs[b_row][b_c4] = bv;
        __syncthreads();

        #pragma unroll
        for (int k = 0; k < 8; k++) {
            float4 a0 = *(float4*)&As[k][tr * 8];
            float4 a1 = *(float4*)&As[k][tr * 8 + 4];
            float4 b0 = *(float4*)&Bs[k][tc * 8];
            float4 b1 = *(float4*)&Bs[k][tc * 8 + 4];
            float af[8] = {a0.x,a0.y,a0.z,a0.w,a1.x,a1.y,a1.z,a1.w};
            float bf[8] = {b0.x,b0.y,b0.z,b0.w,b1.x,b1.y,b1.z,b1.w};
            #pragma unroll
            for (int i = 0; i < 8; i++)
                #pragma unroll
                for (int j = 0; j < 8; j++)
                    acc[i][j] += af[i] * bf[j];
        }
        __syncthreads();
    }

    #pragma unroll
    for (int i = 0; i < 8; i++) {
        int gm = bm + tr * 8 + i;
        #pragma unroll
        for (int j = 0; j < 8; j++) {
            int gn = bn + tc * 8 + j;
            float val = acc[i][j] + bias[gn];
            if (MODE == 0) {
                C[(size_t)gm * N + gn] = val;
            } else {
                int part = gn >> 10;
                int col  = gn & 1023;
                int h = col >> 6, d = col & 63;
                int b = gm >> 11, s = gm & 2047;
                size_t idx = (((size_t)(b * HH + h)) * SS + s) * HD + d;
                float* dst = (part == 0) ? qo : (part == 1) ? pk : pv;
                dst[idx] = val;
            }
        }
    }
}

// ---------------------------------------------------------------------------
// Flash attention v3: register-blocked. BM=128 q/block, BN=128 k/tile,
// 256 threads (16x16). Each thread: 8x8 S-tile, 8 rows x 4 O-cols.
// ---------------------------------------------------------------------------
#define QS_LD 132   // Qs[d][m], d=0..63
#define KS_LD 132   // Ks[d][n]
#define VS_LD 68    // Vs[n][c], n=0..127
#define PS_LD 132   // Ps[m][n]

#define SM_QS 0
#define SM_KS (SM_QS + 64*QS_LD)            // 8448
#define SM_VS (SM_KS + 64*KS_LD)            // 16896
#define SM_PS (SM_VS + 128*VS_LD)           // 25600
#define SM_TOTAL_F (SM_PS + 128*PS_LD)      // 42496 floats = 169984 B

__global__ __launch_bounds__(256, 1) void attn_kernel(
    const float* __restrict__ Q, const float* __restrict__ Kg,
    const float* __restrict__ Vg, float* __restrict__ Og)
{
    extern __shared__ float sm[];
    float* Qs = sm + SM_QS;
    float* Ks = sm + SM_KS;
    float* Vs = sm + SM_VS;
    float* Ps = sm + SM_PS;

    const int qt = 15 - blockIdx.x;   // heavy blocks first
    const int bh = blockIdx.y;
    const int q0 = qt * 128;

    const float* qb = Q  + ((size_t)bh * SS + q0) * HD;
    const float* kb = Kg + (size_t)bh * SS * HD;
    const float* vb = Vg + (size_t)bh * SS * HD;

    const int tid = threadIdx.x;
    const int tr = tid >> 4;     // 0..15
    const int tc = tid & 15;     // 0..15

    // Load Q tile (128x64) transposed into Qs[d][m]: 2048 float4s
    #pragma unroll
    for (int it = 0; it < 8; it++) {
        int e = tid + it * 256;
        int m = e >> 4, c4 = (e & 15) << 2;
        float4 v = *(const float4*)(qb + m * 64 + c4);
        Qs[(c4 + 0) * QS_LD + m] = v.x;
        Qs[(c4 + 1) * QS_LD + m] = v.y;
        Qs[(c4 + 2) * QS_LD + m] = v.z;
        Qs[(c4 + 3) * QS_LD + m] = v.w;
    }

    float m_i[8], l_i[8], o[8][4];
    #pragma unroll
    for (int i = 0; i < 8; i++) {
        m_i[i] = -1e30f; l_i[i] = 0.f;
        #pragma unroll
        for (int c = 0; c < 4; c++) o[i][c] = 0.f;
    }

    for (int kt = 0; kt <= qt; kt++) {
        const int k0 = kt * 128;
        __syncthreads();   // protect Ks/Vs from previous iteration's readers

        // Load K tile (128x64) transposed into Ks[d][n]
        #pragma unroll
        for (int it = 0; it < 8; it++) {
            int e = tid + it * 256;
            int n = e >> 4, c4 = (e & 15) << 2;
            float4 v = *(const float4*)(kb + (size_t)(k0 + n) * 64 + c4);
            Ks[(c4 + 0) * KS_LD + n] = v.x;
            Ks[(c4 + 1) * KS_LD + n] = v.y;
            Ks[(c4 + 2) * KS_LD + n] = v.z;
            Ks[(c4 + 3) * KS_LD + n] = v.w;
        }
        // Load V tile (128x64) natural into Vs[n][c]
        #pragma unroll
        for (int it = 0; it < 8; it++) {
            int e = tid + it * 256;
            int n = e >> 4, c4 = (e & 15) << 2;
            float4 v = *(const float4*)(vb + (size_t)(k0 + n) * 64 + c4);
            *(float4*)&Vs[n * VS_LD + c4] = v;
        }
        __syncthreads();

        // S = Q @ K^T : 8x8 per thread
        float acc[8][8];
        #pragma unroll
        for (int i = 0; i < 8; i++)
            #pragma unroll
            for (int j = 0; j < 8; j++) acc[i][j] = 0.f;

        #pragma unroll 8
        for (int d = 0; d < 64; d++) {
            float4 a0 = *(float4*)&Qs[d * QS_LD + tr * 8];
            float4 a1 = *(float4*)&Qs[d * QS_LD + tr * 8 + 4];
            float4 b0 = *(float4*)&Ks[d * KS_LD + tc * 8];
            float4 b1 = *(float4*)&Ks[d * KS_LD + tc * 8 + 4];
            float af[8] = {a0.x,a0.y,a0.z,a0.w,a1.x,a1.y,a1.z,a1.w};
            float bf[8] = {b0.x,b0.y,b0.z,b0.w,b1.x,b1.y,b1.z,b1.w};
            #pragma unroll
            for (int i = 0; i < 8; i++)
                #pragma unroll
                for (int j = 0; j < 8; j++)
                    acc[i][j] += af[i] * bf[j];
        }

        // scale + causal mask (diagonal tile only needs masking)
        if (kt == qt) {
            #pragma unroll
            for (int i = 0; i < 8; i++) {
                int qi = q0 + tr * 8 + i;
                #pragma unroll
                for (int j = 0; j < 8; j++) {
                    int jg = k0 + tc * 8 + j;
                    acc[i][j] = (jg <= qi) ? acc[i][j] * 0.125f : -1e10f;
                }
            }
        } else {
            #pragma unroll
            for (int i = 0; i < 8; i++)
                #pragma unroll
                for (int j = 0; j < 8; j++)
                    acc[i][j] *= 0.125f;
        }

        // online softmax update
        #pragma unroll
        for (int i = 0; i < 8; i++) {
            float rm = acc[i][0];
            #pragma unroll
            for (int j = 1; j < 8; j++) rm = fmaxf(rm, acc[i][j]);
            #pragma unroll
            for (int off = 1; off < 16; off <<= 1)
                rm = fmaxf(rm, __shfl_xor_sync(0xffffffffu, rm, off));
            float m_new = fmaxf(m_i[i], rm);
            float scale = __expf(m_i[i] - m_new);
            float rs = 0.f;
            #pragma unroll
            for (int j = 0; j < 8; j++) {
                acc[i][j] = __expf(acc[i][j] - m_new);
                rs += acc[i][j];
            }
            #pragma unroll
            for (int off = 1; off < 16; off <<= 1)
                rs += __shfl_xor_sync(0xffffffffu, rs, off);
            l_i[i] = l_i[i] * scale + rs;
            m_i[i] = m_new;
            #pragma unroll
            for (int c = 0; c < 4; c++) o[i][c] *= scale;
        }

        // store P to smem
        #pragma unroll
        for (int i = 0; i < 8; i++) {
            float4 p0 = {acc[i][0], acc[i][1], acc[i][2], acc[i][3]};
            float4 p1 = {acc[i][4], acc[i][5], acc[i][6], acc[i][7]};
            *(float4*)&Ps[(tr * 8 + i) * PS_LD + tc * 8]     = p0;
            *(float4*)&Ps[(tr * 8 + i) * PS_LD + tc * 8 + 4] = p1;
        }
        __syncthreads();

        // O += P @ V  (rows tr*8+i, cols tc*4..tc*4+3)
        #pragma unroll 2
        for (int n0 = 0; n0 < 128; n0 += 4) {
            float4 pr[8];
            #pragma unroll
            for (int i = 0; i < 8; i++)
                pr[i] = *(float4*)&Ps[(tr * 8 + i) * PS_LD + n0];
            #pragma unroll
            for (int t = 0; t < 4; t++) {
                float4 vv = *(float4*)&Vs[(n0 + t) * VS_LD + tc * 4];
                #pragma unroll
                for (int i = 0; i < 8; i++) {
                    float pv = (t == 0) ? pr[i].x : (t == 1) ? pr[i].y
                             : (t == 2) ? pr[i].z : pr[i].w;
                    o[i][0] += pv * vv.x;
                    o[i][1] += pv * vv.y;
                    o[i][2] += pv * vv.z;
                    o[i][3] += pv * vv.w;
                }
            }
        }
    }

    // write merged (B,S,D)
    const int b = bh >> 4, h = bh & 15;
    #pragma unroll
    for (int i = 0; i < 8; i++) {
        float inv = 1.f / l_i[i];
        float4 r = {o[i][0]*inv, o[i][1]*inv, o[i][2]*inv, o[i][3]*inv};
        size_t row = (size_t)(b * SS + q0 + tr * 8 + i);
        *(float4*)(Og + row * DD + h * HD + tc * 4) = r;
    }
}

// ---------------------------------------------------------------------------
extern "C" void kernel_launch(void* const* d_in, const int* in_sizes, int n_in,
                              void* d_out, int out_size)
{
    const float* x        = (const float*)d_in[0];
    const float* c_attn_w = (const float*)d_in[1];
    const float* c_attn_b = (const float*)d_in[2];
    const float* c_proj_w = (const float*)d_in[3];
    const float* c_proj_b = (const float*)d_in[4];

    float* out   = (float*)d_out;
    float* a_out = out;
    float* pk    = out + A_ELEMS;
    float* pv    = pk + KV_ELEMS;

    float* qsym;
    cudaGetSymbolAddress((void**)&qsym, g_q);
    float* asym;
    cudaGetSymbolAddress((void**)&asym, g_attn);

    static const size_t attn_smem = SM_TOTAL_F * sizeof(float);
    cudaFuncSetAttribute(attn_kernel,
                         cudaFuncAttributeMaxDynamicSharedMemorySize,
                         (int)attn_smem);

    // 1) qkv = x @ c_attn_w + b -> scatter
    {
        dim3 grid(3 * DD / 128, MTOT / 128);
        sgemm_kernel<1><<<grid, 256>>>(x, c_attn_w, c_attn_b,
                                       nullptr, pk, pv, qsym,
                                       MTOT, 3 * DD, DD);
    }
    // 2) attention
    {
        dim3 grid(SS / 128, BB * HH);   // (16, 32)
        attn_kernel<<<grid, 256, attn_smem>>>(qsym, pk, pv, asym);
    }
    // 3) proj
    {
        dim3 grid(DD / 128, MTOT / 128);
        sgemm_kernel<0><<<grid, 256>>>(asym, c_proj_w, c_proj_b,
                                       a_out, nullptr, nullptr, nullptr,
                                       MTOT, DD, DD);
    }
}

// round 5
// speedup vs baseline: 5.4073x; 1.5852x over previous
#include <cuda_runtime.h>
#include <cuda_bf16.h>
#include <cstdint>

// Problem constants
#define BB 2
#define SS 2048
#define DD 1024
#define HH 16
#define HD 64
#define MTOT (BB*SS)           // 4096
#define A_ELEMS (MTOT*DD)      // 4,194,304
#define KV_ELEMS (BB*HH*SS*HD) // 4,194,304

// Scratch (device globals; no allocation allowed)
__device__ float g_q[KV_ELEMS];                 // q in (B,H,S,hd) fp32
__device__ __nv_bfloat16 g_w1h[3072*1024];      // c_attn_w^T (N,K) hi
__device__ __nv_bfloat16 g_w1l[3072*1024];      // lo
__device__ __nv_bfloat16 g_w2h[1024*1024];      // c_proj_w^T (N,K) hi
__device__ __nv_bfloat16 g_w2l[1024*1024];
__device__ __nv_bfloat16 g_xh[A_ELEMS];         // x hi (M,K)
__device__ __nv_bfloat16 g_xl[A_ELEMS];
__device__ __nv_bfloat16 g_ah[A_ELEMS];         // attn out hi (M,K)
__device__ __nv_bfloat16 g_al[A_ELEMS];

// ---------------------------------------------------------------------------
// Portable PTX helpers (compute_103 baseline: mma.sync / ldmatrix / cp.async)
// ---------------------------------------------------------------------------
__device__ __forceinline__ uint32_t smem_u32(const void* p) {
    uint32_t a;
    asm("{ .reg .u64 t; cvta.to.shared.u64 t, %1; cvt.u32.u64 %0, t; }"
        : "=r"(a) : "l"(p));
    return a;
}
__device__ __forceinline__ void cp_async16(uint32_t saddr, const void* gptr) {
    asm volatile("cp.async.ca.shared.global [%0], [%1], 16;"
                 :: "r"(saddr), "l"(gptr));
}
__device__ __forceinline__ void cp_commit() {
    asm volatile("cp.async.commit_group;");
}
template<int N>
__device__ __forceinline__ void cp_wait() {
    asm volatile("cp.async.wait_group %0;" :: "n"(N));
}
__device__ __forceinline__ void ldsm4(uint32_t r[4], uint32_t addr) {
    asm volatile("ldmatrix.sync.aligned.m8n8.x4.shared.b16 {%0,%1,%2,%3}, [%4];"
                 : "=r"(r[0]), "=r"(r[1]), "=r"(r[2]), "=r"(r[3]) : "r"(addr));
}
__device__ __forceinline__ void mma_bf16(float d[4], const uint32_t a[4],
                                         uint32_t b0, uint32_t b1) {
    asm volatile("mma.sync.aligned.m16n8k16.row.col.f32.bf16.bf16.f32 "
                 "{%0,%1,%2,%3}, {%4,%5,%6,%7}, {%8,%9}, {%0,%1,%2,%3};"
                 : "+f"(d[0]), "+f"(d[1]), "+f"(d[2]), "+f"(d[3])
                 : "r"(a[0]), "r"(a[1]), "r"(a[2]), "r"(a[3]),
                   "r"(b0), "r"(b1));
}

// ---------------------------------------------------------------------------
// Conversion kernels
// ---------------------------------------------------------------------------
// W (K,N) fp32 -> hi/lo bf16 transposed to (N,K)
__global__ __launch_bounds__(256) void conv_w(
    const float* __restrict__ W, __nv_bfloat16* __restrict__ hi,
    __nv_bfloat16* __restrict__ lo, int K, int N)
{
    __shared__ float t[32][33];
    const int nt = blockIdx.x * 32, kt = blockIdx.y * 32;
    const int tx = threadIdx.x & 31, ty = threadIdx.x >> 5;   // ty 0..7
    #pragma unroll
    for (int j = 0; j < 4; j++)
        t[ty + j*8][tx] = W[(size_t)(kt + ty + j*8) * N + nt + tx];
    __syncthreads();
    #pragma unroll
    for (int j = 0; j < 4; j++) {
        int n = nt + ty + j*8, k = kt + tx;
        float v = t[tx][ty + j*8];
        __nv_bfloat16 h = __float2bfloat16(v);
        float r = v - __bfloat162float(h);
        hi[(size_t)n * K + k] = h;
        lo[(size_t)n * K + k] = __float2bfloat16(r);
    }
}

// elementwise split fp32 -> hi/lo bf16 (4 elems/thread)
__global__ __launch_bounds__(256) void conv_split(
    const float* __restrict__ X, __nv_bfloat16* __restrict__ hi,
    __nv_bfloat16* __restrict__ lo)
{
    int i = (blockIdx.x * 256 + threadIdx.x) * 4;
    float4 v = *(const float4*)(X + i);
    __nv_bfloat16 h0 = __float2bfloat16(v.x), h1 = __float2bfloat16(v.y);
    __nv_bfloat16 h2 = __float2bfloat16(v.z), h3 = __float2bfloat16(v.w);
    __nv_bfloat162 a; a.x = h0; a.y = h1;
    __nv_bfloat162 b; b.x = h2; b.y = h3;
    *(__nv_bfloat162*)(hi + i)     = a;
    *(__nv_bfloat162*)(hi + i + 2) = b;
    __nv_bfloat162 c, d;
    c.x = __float2bfloat16(v.x - __bfloat162float(h0));
    c.y = __float2bfloat16(v.y - __bfloat162float(h1));
    d.x = __float2bfloat16(v.z - __bfloat162float(h2));
    d.y = __float2bfloat16(v.w - __bfloat162float(h3));
    *(__nv_bfloat162*)(lo + i)     = c;
    *(__nv_bfloat162*)(lo + i + 2) = d;
}

// ---------------------------------------------------------------------------
// mma.sync GEMM, bf16x3 split. 128x128x32 tile, 8 warps (4x2), warp 32x64.
// A: (M,K) hi/lo bf16 row-major. B: (N,K) hi/lo bf16 row-major.
// MODE 0: C = A@B^T + bias. MODE 1: scatter qkv.
// ---------------------------------------------------------------------------
#define BK 32
#define AST 40                       // smem row stride in bf16 elems (80 B)
#define TILE_E (128*AST)             // 5120 elems / 10240 B per tile
#define STAGE_E (4*TILE_E)           // Ahi,Alo,Bhi,Blo
#define GEMM_SMEM (2*STAGE_E*2)      // bytes (2 stages)

template<int MODE>
__global__ __launch_bounds__(256, 1) void gemm_mma(
    const __nv_bfloat16* __restrict__ Ahi, const __nv_bfloat16* __restrict__ Alo,
    const __nv_bfloat16* __restrict__ Bhi, const __nv_bfloat16* __restrict__ Blo,
    const float* __restrict__ bias, float* __restrict__ C,
    float* __restrict__ pk, float* __restrict__ pv, float* __restrict__ qo,
    int M, int N, int K)
{
    extern __shared__ __nv_bfloat16 smb[];
    const int tid = threadIdx.x;
    const int lane = tid & 31, wid = tid >> 5;
    const int warp_m = wid >> 1, warp_n = wid & 1;
    const int bm = blockIdx.y * 128, bn = blockIdx.x * 128;
    const uint32_t sb = smem_u32(smb);

    // per-thread cp.async source/dest indices: 2 uint4 per tile
    // e = tid + i*256 ; row = e>>2 ; kcol = (e&3)*8
    const int nstage = K / BK;   // 32

    auto load_stage = [&](int st, int buf) {
        const int kc0 = st * BK;
        uint32_t sbase = sb + (uint32_t)buf * STAGE_E * 2;
        #pragma unroll
        for (int i = 0; i < 2; i++) {
            int e = tid + i * 256;
            int row = e >> 2, kc = (e & 3) * 8;
            uint32_t so = (uint32_t)(row * AST + kc) * 2;
            size_t ga = (size_t)(bm + row) * K + kc0 + kc;
            size_t gb = (size_t)(bn + row) * K + kc0 + kc;
            cp_async16(sbase + 0*TILE_E*2 + so, Ahi + ga);
            cp_async16(sbase + 1*TILE_E*2 + so, Alo + ga);
            cp_async16(sbase + 2*TILE_E*2 + so, Bhi + gb);
            cp_async16(sbase + 3*TILE_E*2 + so, Blo + gb);
        }
        cp_commit();
    };

    float d[2][8][4];
    #pragma unroll
    for (int mf = 0; mf < 2; mf++)
        #pragma unroll
        for (int nf = 0; nf < 8; nf++)
            #pragma unroll
            for (int r = 0; r < 4; r++) d[mf][nf][r] = 0.f;

    load_stage(0, 0);

    // precomputed ldmatrix lane offsets (element units within a tile)
    const int a_row = warp_m * 32 + (lane & 15);
    const int a_kh  = (lane >> 4) * 8;
    const int b_wn  = warp_n * 64;
    const int b_n   = (lane & 7) + ((lane >> 4) * 8);   // within + (mat>>1)*8
    const int b_kh  = ((lane >> 3) & 1) * 8;            // (mat&1)*8

    for (int c = 0; c < nstage; c++) {
        if (c + 1 < nstage) load_stage(c + 1, (c + 1) & 1);
        if (c + 1 < nstage) cp_wait<1>(); else cp_wait<0>();
        __syncthreads();

        uint32_t tbase = sb + (uint32_t)(c & 1) * STAGE_E * 2;
        #pragma unroll
        for (int ks = 0; ks < 2; ks++) {
            const int ko = ks * 16;
            uint32_t ah[2][4], al[2][4];
            #pragma unroll
            for (int mf = 0; mf < 2; mf++) {
                uint32_t off = (uint32_t)((a_row + mf * 16) * AST + ko + a_kh) * 2;
                ldsm4(ah[mf], tbase + 0*TILE_E*2 + off);
                ldsm4(al[mf], tbase + 1*TILE_E*2 + off);
            }
            uint32_t bh[4][4], bl[4][4];
            #pragma unroll
            for (int q = 0; q < 4; q++) {
                uint32_t off = (uint32_t)((b_wn + q * 16 + b_n) * AST + ko + b_kh) * 2;
                ldsm4(bh[q], tbase + 2*TILE_E*2 + off);
                ldsm4(bl[q], tbase + 3*TILE_E*2 + off);
            }
            #pragma unroll
            for (int mf = 0; mf < 2; mf++)
                #pragma unroll
                for (int nf = 0; nf < 8; nf++) {
                    int q = nf >> 1, p = (nf & 1) * 2;
                    mma_bf16(d[mf][nf], ah[mf], bh[q][p], bh[q][p+1]);
                    mma_bf16(d[mf][nf], ah[mf], bl[q][p], bl[q][p+1]);
                    mma_bf16(d[mf][nf], al[mf], bh[q][p], bh[q][p+1]);
                }
        }
        __syncthreads();
    }

    // Epilogue: thread holds (row = g, g+8) x (col pair) per frag
    const int er = lane >> 2;          // 0..7
    const int ec = (lane & 3) * 2;     // 0,2,4,6
    #pragma unroll
    for (int mf = 0; mf < 2; mf++) {
        #pragma unroll
        for (int half = 0; half < 2; half++) {
            int gm = bm + warp_m * 32 + mf * 16 + er + half * 8;
            #pragma unroll
            for (int nf = 0; nf < 8; nf++) {
                int gn = bn + warp_n * 64 + nf * 8 + ec;
                float v0 = d[mf][nf][half * 2 + 0] + bias[gn];
                float v1 = d[mf][nf][half * 2 + 1] + bias[gn + 1];
                if (MODE == 0) {
                    float2 vv = {v0, v1};
                    *(float2*)(C + (size_t)gm * N + gn) = vv;
                } else {
                    int part = gn >> 10;
                    int col  = gn & 1023;
                    int h = col >> 6, dd = col & 63;
                    int b = gm >> 11, s = gm & 2047;
                    size_t idx = (((size_t)(b * HH + h)) * SS + s) * HD + dd;
                    float* dst = (part == 0) ? qo : (part == 1) ? pk : pv;
                    dst[idx]     = v0;
                    dst[idx + 1] = v1;   // dd+1 in same head (dd even)
                }
            }
        }
    }
}

// ---------------------------------------------------------------------------
// Flash attention (fp32 SIMT) — epilogue writes bf16 hi/lo for proj
// ---------------------------------------------------------------------------
#define QS_LD 132
#define KS_LD 132
#define VS_LD 68
#define PS_LD 132
#define SM_QS 0
#define SM_KS (SM_QS + 64*QS_LD)
#define SM_VS (SM_KS + 64*KS_LD)
#define SM_PS (SM_VS + 128*VS_LD)
#define SM_TOTAL_F (SM_PS + 128*PS_LD)

__global__ __launch_bounds__(256, 1) void attn_kernel(
    const float* __restrict__ Q, const float* __restrict__ Kg,
    const float* __restrict__ Vg,
    __nv_bfloat16* __restrict__ Oh, __nv_bfloat16* __restrict__ Ol)
{
    extern __shared__ float sm[];
    float* Qs = sm + SM_QS;
    float* Ks = sm + SM_KS;
    float* Vs = sm + SM_VS;
    float* Ps = sm + SM_PS;

    const int qt = 15 - blockIdx.x;
    const int bh = blockIdx.y;
    const int q0 = qt * 128;

    const float* qb = Q  + ((size_t)bh * SS + q0) * HD;
    const float* kb = Kg + (size_t)bh * SS * HD;
    const float* vb = Vg + (size_t)bh * SS * HD;

    const int tid = threadIdx.x;
    const int tr = tid >> 4;
    const int tc = tid & 15;

    #pragma unroll
    for (int it = 0; it < 8; it++) {
        int e = tid + it * 256;
        int m = e >> 4, c4 = (e & 15) << 2;
        float4 v = *(const float4*)(qb + m * 64 + c4);
        Qs[(c4 + 0) * QS_LD + m] = v.x;
        Qs[(c4 + 1) * QS_LD + m] = v.y;
        Qs[(c4 + 2) * QS_LD + m] = v.z;
        Qs[(c4 + 3) * QS_LD + m] = v.w;
    }

    float m_i[8], l_i[8], o[8][4];
    #pragma unroll
    for (int i = 0; i < 8; i++) {
        m_i[i] = -1e30f; l_i[i] = 0.f;
        #pragma unroll
        for (int c = 0; c < 4; c++) o[i][c] = 0.f;
    }

    for (int kt = 0; kt <= qt; kt++) {
        const int k0 = kt * 128;
        __syncthreads();

        #pragma unroll
        for (int it = 0; it < 8; it++) {
            int e = tid + it * 256;
            int n = e >> 4, c4 = (e & 15) << 2;
            float4 v = *(const float4*)(kb + (size_t)(k0 + n) * 64 + c4);
            Ks[(c4 + 0) * KS_LD + n] = v.x;
            Ks[(c4 + 1) * KS_LD + n] = v.y;
            Ks[(c4 + 2) * KS_LD + n] = v.z;
            Ks[(c4 + 3) * KS_LD + n] = v.w;
        }
        #pragma unroll
        for (int it = 0; it < 8; it++) {
            int e = tid + it * 256;
            int n = e >> 4, c4 = (e & 15) << 2;
            float4 v = *(const float4*)(vb + (size_t)(k0 + n) * 64 + c4);
            *(float4*)&Vs[n * VS_LD + c4] = v;
        }
        __syncthreads();

        float acc[8][8];
        #pragma unroll
        for (int i = 0; i < 8; i++)
            #pragma unroll
            for (int j = 0; j < 8; j++) acc[i][j] = 0.f;

        #pragma unroll 8
        for (int dd = 0; dd < 64; dd++) {
            float4 a0 = *(float4*)&Qs[dd * QS_LD + tr * 8];
            float4 a1 = *(float4*)&Qs[dd * QS_LD + tr * 8 + 4];
            float4 b0 = *(float4*)&Ks[dd * KS_LD + tc * 8];
            float4 b1 = *(float4*)&Ks[dd * KS_LD + tc * 8 + 4];
            float af[8] = {a0.x,a0.y,a0.z,a0.w,a1.x,a1.y,a1.z,a1.w};
            float bf[8] = {b0.x,b0.y,b0.z,b0.w,b1.x,b1.y,b1.z,b1.w};
            #pragma unroll
            for (int i = 0; i < 8; i++)
                #pragma unroll
                for (int j = 0; j < 8; j++)
                    acc[i][j] += af[i] * bf[j];
        }

        if (kt == qt) {
            #pragma unroll
            for (int i = 0; i < 8; i++) {
                int qi = q0 + tr * 8 + i;
                #pragma unroll
                for (int j = 0; j < 8; j++) {
                    int jg = k0 + tc * 8 + j;
                    acc[i][j] = (jg <= qi) ? acc[i][j] * 0.125f : -1e10f;
                }
            }
        } else {
            #pragma unroll
            for (int i = 0; i < 8; i++)
                #pragma unroll
                for (int j = 0; j < 8; j++)
                    acc[i][j] *= 0.125f;
        }

        #pragma unroll
        for (int i = 0; i < 8; i++) {
            float rm = acc[i][0];
            #pragma unroll
            for (int j = 1; j < 8; j++) rm = fmaxf(rm, acc[i][j]);
            #pragma unroll
            for (int off = 1; off < 16; off <<= 1)
                rm = fmaxf(rm, __shfl_xor_sync(0xffffffffu, rm, off));
            float m_new = fmaxf(m_i[i], rm);
            float scale = __expf(m_i[i] - m_new);
            float rs = 0.f;
            #pragma unroll
            for (int j = 0; j < 8; j++) {
                acc[i][j] = __expf(acc[i][j] - m_new);
                rs += acc[i][j];
            }
            #pragma unroll
            for (int off = 1; off < 16; off <<= 1)
                rs += __shfl_xor_sync(0xffffffffu, rs, off);
            l_i[i] = l_i[i] * scale + rs;
            m_i[i] = m_new;
            #pragma unroll
            for (int c = 0; c < 4; c++) o[i][c] *= scale;
        }

        #pragma unroll
        for (int i = 0; i < 8; i++) {
            float4 p0 = {acc[i][0], acc[i][1], acc[i][2], acc[i][3]};
            float4 p1 = {acc[i][4], acc[i][5], acc[i][6], acc[i][7]};
            *(float4*)&Ps[(tr * 8 + i) * PS_LD + tc * 8]     = p0;
            *(float4*)&Ps[(tr * 8 + i) * PS_LD + tc * 8 + 4] = p1;
        }
        __syncthreads();

        #pragma unroll 2
        for (int n0 = 0; n0 < 128; n0 += 4) {
            float4 pr[8];
            #pragma unroll
            for (int i = 0; i < 8; i++)
                pr[i] = *(float4*)&Ps[(tr * 8 + i) * PS_LD + n0];
            #pragma unroll
            for (int t = 0; t < 4; t++) {
                float4 vv = *(float4*)&Vs[(n0 + t) * VS_LD + tc * 4];
                #pragma unroll
                for (int i = 0; i < 8; i++) {
                    float pv = (t == 0) ? pr[i].x : (t == 1) ? pr[i].y
                             : (t == 2) ? pr[i].z : pr[i].w;
                    o[i][0] += pv * vv.x;
                    o[i][1] += pv * vv.y;
                    o[i][2] += pv * vv.z;
                    o[i][3] += pv * vv.w;
                }
            }
        }
    }

    // write bf16 hi/lo for proj input
    const int b = bh >> 4, h = bh & 15;
    #pragma unroll
    for (int i = 0; i < 8; i++) {
        float inv = 1.f / l_i[i];
        float v0 = o[i][0]*inv, v1 = o[i][1]*inv, v2 = o[i][2]*inv, v3 = o[i][3]*inv;
        size_t off = ((size_t)(b * SS + q0 + tr * 8 + i)) * DD + h * HD + tc * 4;
        __nv_bfloat16 h0 = __float2bfloat16(v0), h1 = __float2bfloat16(v1);
        __nv_bfloat16 h2 = __float2bfloat16(v2), h3 = __float2bfloat16(v3);
        __nv_bfloat162 hh0; hh0.x = h0; hh0.y = h1;
        __nv_bfloat162 hh1; hh1.x = h2; hh1.y = h3;
        *(__nv_bfloat162*)(Oh + off)     = hh0;
        *(__nv_bfloat162*)(Oh + off + 2) = hh1;
        __nv_bfloat162 ll0, ll1;
        ll0.x = __float2bfloat16(v0 - __bfloat162float(h0));
        ll0.y = __float2bfloat16(v1 - __bfloat162float(h1));
        ll1.x = __float2bfloat16(v2 - __bfloat162float(h2));
        ll1.y = __float2bfloat16(v3 - __bfloat162float(h3));
        *(__nv_bfloat162*)(Ol + off)     = ll0;
        *(__nv_bfloat162*)(Ol + off + 2) = ll1;
    }
}

// ---------------------------------------------------------------------------
extern "C" void kernel_launch(void* const* d_in, const int* in_sizes, int n_in,
                              void* d_out, int out_size)
{
    const float* x        = (const float*)d_in[0];
    const float* c_attn_w = (const float*)d_in[1];
    const float* c_attn_b = (const float*)d_in[2];
    const float* c_proj_w = (const float*)d_in[3];
    const float* c_proj_b = (const float*)d_in[4];

    float* out   = (float*)d_out;
    float* a_out = out;
    float* pk    = out + A_ELEMS;
    float* pv    = pk + KV_ELEMS;

    float *qsym;
    __nv_bfloat16 *w1h, *w1l, *w2h, *w2l, *xh, *xl, *ah, *al;
    cudaGetSymbolAddress((void**)&qsym, g_q);
    cudaGetSymbolAddress((void**)&w1h, g_w1h);
    cudaGetSymbolAddress((void**)&w1l, g_w1l);
    cudaGetSymbolAddress((void**)&w2h, g_w2h);
    cudaGetSymbolAddress((void**)&w2l, g_w2l);
    cudaGetSymbolAddress((void**)&xh, g_xh);
    cudaGetSymbolAddress((void**)&xl, g_xl);
    cudaGetSymbolAddress((void**)&ah, g_ah);
    cudaGetSymbolAddress((void**)&al, g_al);

    const size_t attn_smem = SM_TOTAL_F * sizeof(float);
    cudaFuncSetAttribute(attn_kernel, cudaFuncAttributeMaxDynamicSharedMemorySize, (int)attn_smem);
    cudaFuncSetAttribute(gemm_mma<0>, cudaFuncAttributeMaxDynamicSharedMemorySize, GEMM_SMEM);
    cudaFuncSetAttribute(gemm_mma<1>, cudaFuncAttributeMaxDynamicSharedMemorySize, GEMM_SMEM);

    // 0) conversions
    conv_w<<<dim3(3072/32, 1024/32), 256>>>(c_attn_w, w1h, w1l, DD, 3*DD);
    conv_w<<<dim3(1024/32, 1024/32), 256>>>(c_proj_w, w2h, w2l, DD, DD);
    conv_split<<<A_ELEMS/1024, 256>>>(x, xh, xl);

    // 1) qkv = x @ c_attn_w + b -> scatter (mma.sync tensor cores)
    gemm_mma<1><<<dim3(3*DD/128, MTOT/128), 256, GEMM_SMEM>>>(
        xh, xl, w1h, w1l, c_attn_b, nullptr, pk, pv, qsym, MTOT, 3*DD, DD);

    // 2) attention -> bf16 hi/lo
    attn_kernel<<<dim3(SS/128, BB*HH), 256, attn_smem>>>(qsym, pk, pv, ah, al);

    // 3) proj (mma.sync tensor cores)
    gemm_mma<0><<<dim3(DD/128, MTOT/128), 256, GEMM_SMEM>>>(
        ah, al, w2h, w2l, c_proj_b, a_out, nullptr, nullptr, nullptr, MTOT, DD, DD);
}